// round 1
// baseline (speedup 1.0000x reference)
#include <cuda_runtime.h>

// Problem constants
#define BB   16384
#define TT   25
#define DD   128
#define HH   128
#define GG   512    // 4H
#define KKK  256    // D + H
#define OUTD 128
#define MM   32     // batch rows per CTA
#define NT   512    // threads per CTA

// ---------- packed f32x2 helpers (FFMA2: 2 fp32 FMAs per instruction) ----------
__device__ __forceinline__ unsigned long long pack2f(float lo, float hi) {
    unsigned long long r;
    asm("mov.b64 %0, {%1, %2};" : "=l"(r) : "f"(lo), "f"(hi));
    return r;
}
__device__ __forceinline__ void ffma2(unsigned long long &acc,
                                      unsigned long long a,
                                      unsigned long long b) {
    asm("fma.rn.f32x2 %0, %1, %2, %0;" : "+l"(acc) : "l"(a), "l"(b));
}
__device__ __forceinline__ float hsum2(unsigned long long v) {
    float lo, hi;
    asm("mov.b64 {%0, %1}, %2;" : "=f"(lo), "=f"(hi) : "l"(v));
    return lo + hi;
}

__device__ __forceinline__ float sigmoid_f(float x) {
    return __fdividef(1.f, 1.f + __expf(-x));
}
__device__ __forceinline__ float tanh_f(float x) {
    // 1 - 2/(e^{2x}+1); saturates correctly for large |x| (inf -> 1, 0 -> -1)
    return 1.f - __fdividef(2.f, __expf(2.f * x) + 1.f);
}

__global__ __launch_bounds__(NT, 1)
void lstm_agg_kernel(const float* __restrict__ self_vecs,   // [B, D]
                     const float* __restrict__ neig,        // [B, T, D]
                     const float* __restrict__ Wk,          // [D, 4H]
                     const float* __restrict__ Wr,          // [H, 4H]
                     const float* __restrict__ bias,        // [4H]
                     const float* __restrict__ Wself,       // [D, OUT]
                     const float* __restrict__ Wneigh,      // [H, OUT]
                     float* __restrict__ out)               // [B, OUT]
{
    extern __shared__ float smem[];
    float* Xs   = smem;                   // [MM][KKK]  (x_t | h)   32 KB
    float* Zs   = Xs + MM * KKK;          // [MM][GG]   pre-act     64 KB
    float* Cs   = Zs + MM * GG;           // [MM][HH]   cell state  16 KB
    float* Ho   = Cs + MM * HH;           // [MM][HH]   h snapshot  16 KB
    int*   lenS = (int*)(Ho + MM * HH);   // [MM]

    const int tid  = threadIdx.x;
    const int b0   = blockIdx.x * MM;
    const int wid  = tid >> 5;
    const int lane = tid & 31;

    // ---- prepass: per-row sequence lengths (2 rows per warp, exact semantics) ----
    #pragma unroll
    for (int rr = 0; rr < 2; rr++) {
        const int r = wid * 2 + rr;
        const float4* xrow = (const float4*)(neig + (size_t)(b0 + r) * TT * DD);
        int len = 0;
        for (int t = 0; t < TT; t++) {
            float4 v = xrow[t * (DD / 4) + lane];
            bool nz = (v.x != 0.f) || (v.y != 0.f) || (v.z != 0.f) || (v.w != 0.f);
            len += (__ballot_sync(0xffffffffu, nz) != 0u) ? 1 : 0;
        }
        if (lane == 0) lenS[r] = (len > 0) ? len : 1;
    }

    // ---- init h (in Xs) and c to zero ----
    for (int i = tid; i < MM * HH; i += NT) {
        int r = i >> 7, u = i & 127;
        Xs[r * KKK + DD + u] = 0.f;
        Cs[i] = 0.f;
    }
    __syncthreads();

    const float bias_c = bias[tid];   // this thread's output column bias

    // ---- recurrence over T steps ----
    for (int t = 0; t < TT; t++) {
        // load x_t tile into Xs[:, 0:D] (coalesced float4)
        for (int i = tid; i < MM * (DD / 4); i += NT) {
            int r = i >> 5, q = i & 31;
            ((float4*)(Xs + r * KKK))[q] =
                ((const float4*)(neig + ((size_t)(b0 + r) * TT + t) * DD))[q];
        }
        __syncthreads();

        // GEMM: z[r][tid] = bias + sum_k X[r][k] * W[k][tid], packed f32x2 over k
        unsigned long long acc[MM];
        #pragma unroll
        for (int r = 0; r < MM; r++) acc[r] = pack2f(bias_c, 0.f);

        #pragma unroll
        for (int half = 0; half < 2; half++) {
            const float* Wb  = (half == 0 ? Wk : Wr) + tid;
            const int    xoff = half * DD;
            // software prefetch of the next k-quad's weights
            float w0 = Wb[0], w1 = Wb[GG], w2 = Wb[2 * GG], w3 = Wb[3 * GG];
            #pragma unroll 1
            for (int kq = 0; kq < DD / 4; kq++) {
                float n0 = 0.f, n1 = 0.f, n2 = 0.f, n3 = 0.f;
                if (kq < DD / 4 - 1) {
                    const float* Wn = Wb + 4 * GG;
                    n0 = Wn[0]; n1 = Wn[GG]; n2 = Wn[2 * GG]; n3 = Wn[3 * GG];
                }
                const unsigned long long wp0 = pack2f(w0, w1);
                const unsigned long long wp1 = pack2f(w2, w3);
                const float* xb = Xs + xoff + 4 * kq;
                #pragma unroll
                for (int r = 0; r < MM; r++) {
                    // contiguous k-pairs: one LDS.128 = two packed operands
                    ulonglong2 xv = *reinterpret_cast<const ulonglong2*>(xb + r * KKK);
                    ffma2(acc[r], xv.x, wp0);
                    ffma2(acc[r], xv.y, wp1);
                }
                w0 = n0; w1 = n1; w2 = n2; w3 = n3;
                Wb += 4 * GG;
            }
        }

        #pragma unroll
        for (int r = 0; r < MM; r++) Zs[r * GG + tid] = hsum2(acc[r]);
        __syncthreads();

        // gates + state update (8 (row,unit) pairs per thread, conflict-free)
        #pragma unroll
        for (int j = 0; j < (MM * HH) / NT; j++) {
            int idx = tid + j * NT;
            int r = idx >> 7, u = idx & 127;
            float zi = Zs[r * GG + u];
            float zf = Zs[r * GG + u + HH];
            float zg = Zs[r * GG + u + 2 * HH];
            float zo = Zs[r * GG + u + 3 * HH];
            float iv = sigmoid_f(zi);
            float fv = sigmoid_f(zf);
            float gv = tanh_f(zg);
            float ov = sigmoid_f(zo);
            float c  = fv * Cs[idx] + iv * gv;
            Cs[idx]  = c;
            float h  = ov * tanh_f(c);
            Xs[r * KKK + DD + u] = h;             // next step's recurrent input
            if (t == lenS[r] - 1) Ho[idx] = h;    // hs[length-1] snapshot
        }
        __syncthreads();
    }

    // ---- epilogue: out = relu(self @ Wself + h_sel @ Wneigh) ----
    for (int i = tid; i < MM * (DD / 4); i += NT) {
        int r = i >> 5, q = i & 31;
        ((float4*)(Xs + r * KKK))[q] =
            ((const float4*)(self_vecs + (size_t)(b0 + r) * DD))[q];
    }
    __syncthreads();

    #pragma unroll
    for (int j = 0; j < 2; j++) {
        int idx = tid + j * NT;             // 1024 float4 outputs = 32 rows x 32 groups
        int r   = idx >> 5;
        int o4  = idx & 31;
        float4 a = make_float4(0.f, 0.f, 0.f, 0.f);
        for (int d = 0; d < DD; d++) {
            float x  = Xs[r * KKK + d];
            float4 w = ((const float4*)(Wself + d * OUTD))[o4];
            a.x += x * w.x; a.y += x * w.y; a.z += x * w.z; a.w += x * w.w;
        }
        for (int u = 0; u < HH; u++) {
            float h  = Ho[r * HH + u];
            float4 w = ((const float4*)(Wneigh + u * OUTD))[o4];
            a.x += h * w.x; a.y += h * w.y; a.z += h * w.z; a.w += h * w.w;
        }
        float4* op = ((float4*)(out + (size_t)(b0 + r) * OUTD)) + o4;
        *op = make_float4(fmaxf(a.x, 0.f), fmaxf(a.y, 0.f),
                          fmaxf(a.z, 0.f), fmaxf(a.w, 0.f));
    }
}

extern "C" void kernel_launch(void* const* d_in, const int* in_sizes, int n_in,
                              void* d_out, int out_size) {
    const float* self_vecs = (const float*)d_in[0];
    const float* neig      = (const float*)d_in[1];
    const float* Wk        = (const float*)d_in[2];
    const float* Wr        = (const float*)d_in[3];
    const float* bias      = (const float*)d_in[4];
    const float* Wself     = (const float*)d_in[5];
    const float* Wneigh    = (const float*)d_in[6];
    float* out = (float*)d_out;

    const int smem_bytes = (MM * KKK + MM * GG + 2 * MM * HH) * 4 + MM * 4; // 131200 B
    cudaFuncSetAttribute(lstm_agg_kernel,
                         cudaFuncAttributeMaxDynamicSharedMemorySize, smem_bytes);

    lstm_agg_kernel<<<BB / MM, NT, smem_bytes>>>(
        self_vecs, neig, Wk, Wr, bias, Wself, Wneigh, out);
}

// round 2
// speedup vs baseline: 1.0000x; 1.0000x over previous
#include <cuda_runtime.h>

// Problem constants
#define BB   16384
#define TT   25
#define DD   128
#define HH   128
#define GG   512    // 4H
#define KKK  256    // D + H
#define OUTD 128
#define MM   32     // batch rows per CTA
#define NT   512    // threads per CTA

// ---------- packed f32x2 helpers (FFMA2: 2 fp32 FMAs per instruction) ----------
__device__ __forceinline__ unsigned long long pack2f(float lo, float hi) {
    unsigned long long r;
    asm("mov.b64 %0, {%1, %2};" : "=l"(r) : "f"(lo), "f"(hi));
    return r;
}
__device__ __forceinline__ void ffma2(unsigned long long &acc,
                                      unsigned long long a,
                                      unsigned long long b) {
    asm("fma.rn.f32x2 %0, %1, %2, %0;" : "+l"(acc) : "l"(a), "l"(b));
}
__device__ __forceinline__ float hsum2(unsigned long long v) {
    float lo, hi;
    asm("mov.b64 {%0, %1}, %2;" : "=f"(lo), "=f"(hi) : "l"(v));
    return lo + hi;
}

__device__ __forceinline__ float sigmoid_f(float x) {
    return __fdividef(1.f, 1.f + __expf(-x));
}
__device__ __forceinline__ float tanh_f(float x) {
    // 1 - 2/(e^{2x}+1); saturates correctly for large |x| (inf -> 1, 0 -> -1)
    return 1.f - __fdividef(2.f, __expf(2.f * x) + 1.f);
}

__global__ __launch_bounds__(NT, 1)
void lstm_agg_kernel(const float* __restrict__ self_vecs,   // [B, D]
                     const float* __restrict__ neig,        // [B, T, D]
                     const float* __restrict__ Wk,          // [D, 4H]
                     const float* __restrict__ Wr,          // [H, 4H]
                     const float* __restrict__ bias,        // [4H]
                     const float* __restrict__ Wself,       // [D, OUT]
                     const float* __restrict__ Wneigh,      // [H, OUT]
                     float* __restrict__ out)               // [B, OUT]
{
    extern __shared__ float smem[];
    float* Xs   = smem;                   // [MM][KKK]  (x_t | h)   32 KB
    float* Zs   = Xs + MM * KKK;          // [MM][GG]   pre-act     64 KB
    float* Cs   = Zs + MM * GG;           // [MM][HH]   cell state  16 KB
    float* Ho   = Cs + MM * HH;           // [MM][HH]   h snapshot  16 KB
    int*   lenS = (int*)(Ho + MM * HH);   // [MM]

    const int tid  = threadIdx.x;
    const int b0   = blockIdx.x * MM;
    const int wid  = tid >> 5;
    const int lane = tid & 31;

    // ---- prepass: per-row sequence lengths (2 rows per warp, exact semantics) ----
    #pragma unroll
    for (int rr = 0; rr < 2; rr++) {
        const int r = wid * 2 + rr;
        const float4* xrow = (const float4*)(neig + (size_t)(b0 + r) * TT * DD);
        int len = 0;
        for (int t = 0; t < TT; t++) {
            float4 v = xrow[t * (DD / 4) + lane];
            bool nz = (v.x != 0.f) || (v.y != 0.f) || (v.z != 0.f) || (v.w != 0.f);
            len += (__ballot_sync(0xffffffffu, nz) != 0u) ? 1 : 0;
        }
        if (lane == 0) lenS[r] = (len > 0) ? len : 1;
    }

    // ---- init h (in Xs) and c to zero ----
    for (int i = tid; i < MM * HH; i += NT) {
        int r = i >> 7, u = i & 127;
        Xs[r * KKK + DD + u] = 0.f;
        Cs[i] = 0.f;
    }
    __syncthreads();

    const float bias_c = bias[tid];   // this thread's output column bias

    // ---- recurrence over T steps ----
    for (int t = 0; t < TT; t++) {
        // load x_t tile into Xs[:, 0:D] (coalesced float4)
        for (int i = tid; i < MM * (DD / 4); i += NT) {
            int r = i >> 5, q = i & 31;
            ((float4*)(Xs + r * KKK))[q] =
                ((const float4*)(neig + ((size_t)(b0 + r) * TT + t) * DD))[q];
        }
        __syncthreads();

        // GEMM: z[r][tid] = bias + sum_k X[r][k] * W[k][tid], packed f32x2 over k
        unsigned long long acc[MM];
        #pragma unroll
        for (int r = 0; r < MM; r++) acc[r] = pack2f(bias_c, 0.f);

        #pragma unroll
        for (int half = 0; half < 2; half++) {
            const float* Wb  = (half == 0 ? Wk : Wr) + tid;
            const int    xoff = half * DD;
            // software prefetch of the next k-quad's weights
            float w0 = Wb[0], w1 = Wb[GG], w2 = Wb[2 * GG], w3 = Wb[3 * GG];
            #pragma unroll 1
            for (int kq = 0; kq < DD / 4; kq++) {
                float n0 = 0.f, n1 = 0.f, n2 = 0.f, n3 = 0.f;
                if (kq < DD / 4 - 1) {
                    const float* Wn = Wb + 4 * GG;
                    n0 = Wn[0]; n1 = Wn[GG]; n2 = Wn[2 * GG]; n3 = Wn[3 * GG];
                }
                const unsigned long long wp0 = pack2f(w0, w1);
                const unsigned long long wp1 = pack2f(w2, w3);
                const float* xb = Xs + xoff + 4 * kq;
                #pragma unroll
                for (int r = 0; r < MM; r++) {
                    // contiguous k-pairs: one LDS.128 = two packed operands
                    ulonglong2 xv = *reinterpret_cast<const ulonglong2*>(xb + r * KKK);
                    ffma2(acc[r], xv.x, wp0);
                    ffma2(acc[r], xv.y, wp1);
                }
                w0 = n0; w1 = n1; w2 = n2; w3 = n3;
                Wb += 4 * GG;
            }
        }

        #pragma unroll
        for (int r = 0; r < MM; r++) Zs[r * GG + tid] = hsum2(acc[r]);
        __syncthreads();

        // gates + state update (8 (row,unit) pairs per thread, conflict-free)
        #pragma unroll
        for (int j = 0; j < (MM * HH) / NT; j++) {
            int idx = tid + j * NT;
            int r = idx >> 7, u = idx & 127;
            float zi = Zs[r * GG + u];
            float zf = Zs[r * GG + u + HH];
            float zg = Zs[r * GG + u + 2 * HH];
            float zo = Zs[r * GG + u + 3 * HH];
            float iv = sigmoid_f(zi);
            float fv = sigmoid_f(zf);
            float gv = tanh_f(zg);
            float ov = sigmoid_f(zo);
            float c  = fv * Cs[idx] + iv * gv;
            Cs[idx]  = c;
            float h  = ov * tanh_f(c);
            Xs[r * KKK + DD + u] = h;             // next step's recurrent input
            if (t == lenS[r] - 1) Ho[idx] = h;    // hs[length-1] snapshot
        }
        __syncthreads();
    }

    // ---- epilogue: out = relu(self @ Wself + h_sel @ Wneigh) ----
    for (int i = tid; i < MM * (DD / 4); i += NT) {
        int r = i >> 5, q = i & 31;
        ((float4*)(Xs + r * KKK))[q] =
            ((const float4*)(self_vecs + (size_t)(b0 + r) * DD))[q];
    }
    __syncthreads();

    #pragma unroll
    for (int j = 0; j < 2; j++) {
        int idx = tid + j * NT;             // 1024 float4 outputs = 32 rows x 32 groups
        int r   = idx >> 5;
        int o4  = idx & 31;
        float4 a = make_float4(0.f, 0.f, 0.f, 0.f);
        for (int d = 0; d < DD; d++) {
            float x  = Xs[r * KKK + d];
            float4 w = ((const float4*)(Wself + d * OUTD))[o4];
            a.x += x * w.x; a.y += x * w.y; a.z += x * w.z; a.w += x * w.w;
        }
        for (int u = 0; u < HH; u++) {
            float h  = Ho[r * HH + u];
            float4 w = ((const float4*)(Wneigh + u * OUTD))[o4];
            a.x += h * w.x; a.y += h * w.y; a.z += h * w.z; a.w += h * w.w;
        }
        float4* op = ((float4*)(out + (size_t)(b0 + r) * OUTD)) + o4;
        *op = make_float4(fmaxf(a.x, 0.f), fmaxf(a.y, 0.f),
                          fmaxf(a.z, 0.f), fmaxf(a.w, 0.f));
    }
}

extern "C" void kernel_launch(void* const* d_in, const int* in_sizes, int n_in,
                              void* d_out, int out_size) {
    const float* self_vecs = (const float*)d_in[0];
    const float* neig      = (const float*)d_in[1];
    const float* Wk        = (const float*)d_in[2];
    const float* Wr        = (const float*)d_in[3];
    const float* bias      = (const float*)d_in[4];
    const float* Wself     = (const float*)d_in[5];
    const float* Wneigh    = (const float*)d_in[6];
    float* out = (float*)d_out;

    const int smem_bytes = (MM * KKK + MM * GG + 2 * MM * HH) * 4 + MM * 4; // 131200 B
    cudaFuncSetAttribute(lstm_agg_kernel,
                         cudaFuncAttributeMaxDynamicSharedMemorySize, smem_bytes);

    lstm_agg_kernel<<<BB / MM, NT, smem_bytes>>>(
        self_vecs, neig, Wk, Wr, bias, Wself, Wneigh, out);
}